// round 14
// baseline (speedup 1.0000x reference)
#include <cuda_runtime.h>
#include <cuda_fp16.h>

#define BATCH 128
#define NTF 1024
#define NGENES 20000
#define NQUADS (NGENES / 4)          // 5000 gene-quads
#define NEDGE1 (NGENES * 64)         // 1,280,000 layer-1 edges
#define NEDGE_HALF (NEDGE1 / 2)
#define CHUNK 64                     // batch elements per block
#define THREADS 1024                 // 32 warps
#define GRID 148                     // one wave, 74 blocks per chunk
#define WARPS_PER_CHUNK 2368
#define SMEM_BYTES (NTF * CHUNK * 2) // 131072
#define TAIL_W (NQUADS - 2 * WARPS_PER_CHUNK)   // 264

// device scratch
__device__ __half g_xTh[NTF * BATCH];       // transposed fp16 features
__device__ unsigned int g_off[NEDGE1];      // pre-scaled byte offsets (idx*128)
__device__ __half g_w1h[NEDGE1];            // fp16 layer-1 weights
__device__ uint4  g_tail[NGENES * 4];       // 64B/gene packed tail
__device__ __half g_yTh[NGENES * BATCH];    // gene-major fp16 output

__device__ __forceinline__ unsigned int packh2(float a, float b) {
    const __half2 h = __float22half2_rn(make_float2(a, b));
    return *reinterpret_cast<const unsigned int*>(&h);
}

// ---- prep A/B: offset + w1h tables, 16 edges/thread, half per launch ----
__global__ void prep_edges(const int* __restrict__ in1,
                           const float* __restrict__ w1, int base) {
    const int e = base + (blockIdx.x * 256 + threadIdx.x) * 16;
    if (e + 16 <= base + NEDGE_HALF) {
        const int4 i0 = __ldg((const int4*)(in1 + e));
        const int4 i1 = __ldg((const int4*)(in1 + e) + 1);
        const int4 i2 = __ldg((const int4*)(in1 + e) + 2);
        const int4 i3 = __ldg((const int4*)(in1 + e) + 3);
        const float4 a0 = __ldg((const float4*)(w1 + e));
        const float4 a1 = __ldg((const float4*)(w1 + e) + 1);
        const float4 a2 = __ldg((const float4*)(w1 + e) + 2);
        const float4 a3 = __ldg((const float4*)(w1 + e) + 3);
        uint4* od = (uint4*)(g_off + e);
        od[0] = make_uint4((unsigned)i0.x << 7, (unsigned)i0.y << 7,
                           (unsigned)i0.z << 7, (unsigned)i0.w << 7);
        od[1] = make_uint4((unsigned)i1.x << 7, (unsigned)i1.y << 7,
                           (unsigned)i1.z << 7, (unsigned)i1.w << 7);
        od[2] = make_uint4((unsigned)i2.x << 7, (unsigned)i2.y << 7,
                           (unsigned)i2.z << 7, (unsigned)i2.w << 7);
        od[3] = make_uint4((unsigned)i3.x << 7, (unsigned)i3.y << 7,
                           (unsigned)i3.z << 7, (unsigned)i3.w << 7);
        uint4 wa, wb;
        wa.x = packh2(a0.x, a0.y); wa.y = packh2(a0.z, a0.w);
        wa.z = packh2(a1.x, a1.y); wa.w = packh2(a1.z, a1.w);
        wb.x = packh2(a2.x, a2.y); wb.y = packh2(a2.z, a2.w);
        wb.z = packh2(a3.x, a3.y); wb.w = packh2(a3.z, a3.w);
        *(uint4*)(g_w1h + e) = wa;
        *(uint4*)(g_w1h + e + 8) = wb;
    }
}

// ---- prep C: feature transpose + tail structs ----
__global__ void prep_feat(const float* __restrict__ f,
                          const float* __restrict__ w2,
                          const float* __restrict__ b1,
                          const float* __restrict__ b2,
                          const float* __restrict__ w3,
                          const float* __restrict__ b3) {
    const int bid = blockIdx.x;
    if (bid < 128) {
        __shared__ float tile[32][33];
        const int tx = threadIdx.x & 31, ty = threadIdx.x >> 5;
        const int t0 = (bid & 31) * 32;   // TF base
        const int b0 = (bid >> 5) * 32;   // batch base
#pragma unroll
        for (int j = 0; j < 32; j += 8)
            tile[ty + j][tx] = f[(b0 + ty + j) * NTF + t0 + tx];
        __syncthreads();
#pragma unroll
        for (int j = 0; j < 32; j += 8)
            g_xTh[(t0 + ty + j) * BATCH + b0 + tx] = __float2half(tile[tx][ty + j]);
    } else {
        const int g = (bid - 128) * 256 + threadIdx.x;
        if (g < NGENES) {
            const float4 q0 = __ldg((const float4*)(w2 + g * 16));
            const float4 q1 = __ldg((const float4*)(w2 + g * 16) + 1);
            const float4 q2 = __ldg((const float4*)(w2 + g * 16) + 2);
            const float4 q3 = __ldg((const float4*)(w2 + g * 16) + 3);
            const float4 b1q = __ldg((const float4*)(b1 + g * 4));
            const float4 b2q = __ldg((const float4*)(b2 + g * 4));
            const float4 w3q = __ldg((const float4*)(w3 + g * 4));
            const float  b3s = __ldg(b3 + g);
            uint4 u0, u1, u2, u3;
            u0.x = packh2(q0.x, q0.y); u0.y = packh2(q0.z, q0.w);
            u0.z = packh2(q1.x, q1.y); u0.w = packh2(q1.z, q1.w);
            u1.x = packh2(q2.x, q2.y); u1.y = packh2(q2.z, q2.w);
            u1.z = packh2(q3.x, q3.y); u1.w = packh2(q3.z, q3.w);
            u2.x = packh2(b1q.x, b1q.y); u2.y = packh2(b1q.z, b1q.w);
            u2.z = packh2(b2q.x, b2q.y); u2.w = packh2(b2q.z, b2q.w);
            u3.x = packh2(w3q.x, w3q.y); u3.y = packh2(w3q.z, w3q.w);
            u3.z = __float_as_uint(b3s);  u3.w = 0u;
            uint4* dst = g_tail + (size_t)g * 4;
            dst[0] = u0; dst[1] = u1; dst[2] = u2; dst[3] = u3;
        }
    }
}

// g_yTh [NGENES][BATCH] fp16 -> out [BATCH][NGENES] fp32
__global__ void transpose_out(float* __restrict__ out) {
    __shared__ float tile[32][33];
    const int tx = threadIdx.x, ty = threadIdx.y;
    const int g0 = blockIdx.x * 32;
    const int b0 = blockIdx.y * 32;
#pragma unroll
    for (int j = 0; j < 32; j += 8)
        tile[ty + j][tx] = __half2float(g_yTh[(size_t)(g0 + ty + j) * BATCH + b0 + tx]);
    __syncthreads();
#pragma unroll
    for (int j = 0; j < 32; j += 8)
        out[(size_t)(b0 + ty + j) * NGENES + g0 + tx] = tile[tx][ty + j];
}

__device__ __forceinline__ __half2 u2h(unsigned int u) {
    return *reinterpret_cast<__half2*>(&u);
}
__device__ __forceinline__ float tanh_mufu(float x) {
    float y;
    asm("tanh.approx.f32 %0, %1;" : "=f"(y) : "f"(x));
    return y;
}
__device__ __forceinline__ __half2 tanh_h2f(float2 a) {
    __half2 h = __float22half2_rn(a);
    unsigned int u = *reinterpret_cast<unsigned int*>(&h), r;
    asm("tanh.approx.f16x2 %0, %1;" : "=r"(r) : "r"(u));
    return u2h(r);
}

// 4 edges: LDS.128 row gathers (8 batches/lane), fp16 chain into acc[4]
__device__ __forceinline__ void group8(const char* fb, uint4 o,
                                       unsigned int wlo, unsigned int whi,
                                       __half2 acc[4], bool init) {
    const uint4 x0 = *(const uint4*)(fb + o.x);
    const uint4 x1 = *(const uint4*)(fb + o.y);
    const uint4 x2 = *(const uint4*)(fb + o.z);
    const uint4 x3 = *(const uint4*)(fb + o.w);
    const __half2 w0 = __low2half2(u2h(wlo));
    const __half2 w1 = __high2half2(u2h(wlo));
    const __half2 w2 = __low2half2(u2h(whi));
    const __half2 w3 = __high2half2(u2h(whi));
    const unsigned int* p0 = (const unsigned int*)&x0;
    const unsigned int* p1 = (const unsigned int*)&x1;
    const unsigned int* p2 = (const unsigned int*)&x2;
    const unsigned int* p3 = (const unsigned int*)&x3;
#pragma unroll
    for (int j = 0; j < 4; j++) {
        __half2 a = init ? __hmul2(w0, u2h(p0[j]))
                         : __hfma2(w0, u2h(p0[j]), acc[j]);
        a = __hfma2(w1, u2h(p1[j]), a);
        a = __hfma2(w2, u2h(p2[j]), a);
        a = __hfma2(w3, u2h(p3[j]), a);
        acc[j] = a;
    }
}

// layer-1 node: 16 edges, two fp16 chains merged by HADD2 (depth-2), fp32 bias
__device__ __forceinline__ void l1_node8(const char* fb, const uint4* op,
                                         const uint4* wp, int n, float bias,
                                         __half2* hout) {
    const uint4 o0 = __ldg(op + 4 * n + 0);
    const uint4 o1 = __ldg(op + 4 * n + 1);
    const uint4 wa = __ldg(wp + 2 * n);
    __half2 a0[4], a1[4];
    group8(fb, o0, wa.x, wa.y, a0, true);
    group8(fb, o1, wa.z, wa.w, a1, true);
    const uint4 o2 = __ldg(op + 4 * n + 2);
    const uint4 o3 = __ldg(op + 4 * n + 3);
    const uint4 wb = __ldg(wp + 2 * n + 1);
    group8(fb, o2, wb.x, wb.y, a0, false);
    group8(fb, o3, wb.z, wb.w, a1, false);
#pragma unroll
    for (int j = 0; j < 4; j++) {
        const __half2 s = __hadd2(a0[j], a1[j]);
        const float2 f = __half22float2(s);
        hout[j] = tanh_h2f(make_float2(f.x + bias, f.y + bias));
    }
}

// layer-2 node (fp16 MAC) + fp32 tanh + fp32 layer-3 accumulate (8 batches)
__device__ __forceinline__ void l23_node8(const __half2* h1, unsigned int wlo,
                                          unsigned int whi, float b2o, float w3o,
                                          float* y) {
    const __half2 bb = __float2half2_rn(b2o);
    const __half2 q0 = __low2half2(u2h(wlo)),  q1 = __high2half2(u2h(wlo));
    const __half2 q2 = __low2half2(u2h(whi)),  q3 = __high2half2(u2h(whi));
#pragma unroll
    for (int j = 0; j < 4; j++) {
        __half2 s = bb;
        s = __hfma2(q0, h1[0 * 4 + j], s);
        s = __hfma2(q1, h1[1 * 4 + j], s);
        s = __hfma2(q2, h1[2 * 4 + j], s);
        s = __hfma2(q3, h1[3 * 4 + j], s);
        const float2 f = __half22float2(s);
        y[2 * j]     = fmaf(w3o, tanh_mufu(f.x), y[2 * j]);
        y[2 * j + 1] = fmaf(w3o, tanh_mufu(f.y), y[2 * j + 1]);
    }
}

// one gene-quad per warp: 4 genes x 8-batch lanes
__device__ __forceinline__ void compute_quad(const char* fb, int quad,
                                             int b0, int lane) {
    const int g = quad * 4 + (lane >> 3);
    const uint4* op = (const uint4*)(g_off + (size_t)g * 64);   // 16 uint4
    const uint4* wp = (const uint4*)(g_w1h + (size_t)g * 64);   // 8 uint4
    const uint4* tp = g_tail + (size_t)g * 4;

    const uint4 u2 = __ldg(tp + 2);   // b1h x4, b2h x4
    const uint4 u3 = __ldg(tp + 3);   // w3h x4, b3 fp32
    const float2 b1a = __half22float2(u2h(u2.x));
    const float2 b1b = __half22float2(u2h(u2.y));

    __half2 h1[16];   // [node][4 x half2] = 8 batches per node
    l1_node8(fb, op, wp, 0, b1a.x, h1 + 0);
    l1_node8(fb, op, wp, 1, b1a.y, h1 + 4);
    const uint4 u0 = __ldg(tp + 0);   // w2h rows 0-1
    const uint4 u1 = __ldg(tp + 1);   // w2h rows 2-3
    l1_node8(fb, op, wp, 2, b1b.x, h1 + 8);
    l1_node8(fb, op, wp, 3, b1b.y, h1 + 12);

    const float2 b2a = __half22float2(u2h(u2.z));
    const float2 b2b = __half22float2(u2h(u2.w));
    const float2 w3a = __half22float2(u2h(u3.x));
    const float2 w3b = __half22float2(u2h(u3.y));
    const float  yb  = __uint_as_float(u3.z);
    float y[8];
#pragma unroll
    for (int i = 0; i < 8; i++) y[i] = yb;
    l23_node8(h1, u0.x, u0.y, b2a.x, w3a.x, y);
    l23_node8(h1, u0.z, u0.w, b2a.y, w3a.y, y);
    l23_node8(h1, u1.x, u1.y, b2b.x, w3b.x, y);
    l23_node8(h1, u1.z, u1.w, b2b.y, w3b.y, y);

    uint4 out;
    out.x = packh2(y[0], y[1]); out.y = packh2(y[2], y[3]);
    out.z = packh2(y[4], y[5]); out.w = packh2(y[6], y[7]);
    *(uint4*)&g_yTh[(size_t)g * BATCH + b0 + (lane & 7) * 8] = out;
}

__global__ void __launch_bounds__(THREADS, 1) fused_kernel() {
    extern __shared__ unsigned int xs[];   // [NTF][32] uint -> 128B fp16 rows
    const int tid = threadIdx.x;
    const int chunk = blockIdx.x & 1;      // 148 blocks -> 74 per chunk
    const int b0 = chunk * CHUNK;

    // fill feature slice (rows of 64 fp16 = 8 uint4)
    {
        const uint4* src = (const uint4*)g_xTh;  // global row = 16 uint4
        uint4* dst = (uint4*)xs;
#pragma unroll
        for (int i = tid; i < NTF * 8; i += THREADS) {
            const int t = i >> 3, c = i & 7;
            dst[i] = src[t * 16 + chunk * 8 + c];
        }
    }
    __syncthreads();

    const int lane = tid & 31;
    const char* fb = (const char*)xs + (lane & 7) * 16;  // lane's 8-batch column
    const int w = (blockIdx.x >> 1) * 32 + (tid >> 5);   // 0..2367 in chunk

    compute_quad(fb, w, b0, lane);
    compute_quad(fb, WARPS_PER_CHUNK + w, b0, lane);
    if (w < TAIL_W)
        compute_quad(fb, 2 * WARPS_PER_CHUNK + w, b0, lane);
}

extern "C" void kernel_launch(void* const* d_in, const int* in_sizes, int n_in,
                              void* d_out, int out_size) {
    const float* features = (const float*)d_in[0];
    const float* w1 = (const float*)d_in[1];
    const float* b1 = (const float*)d_in[2];
    const float* w2 = (const float*)d_in[3];
    const float* b2 = (const float*)d_in[4];
    const float* w3 = (const float*)d_in[5];
    const float* b3 = (const float*)d_in[6];
    const int* in1 = (const int*)d_in[8];
    float* out = (float*)d_out;

    cudaFuncSetAttribute(fused_kernel,
                         cudaFuncAttributeMaxDynamicSharedMemorySize, SMEM_BYTES);

    const int eblocks = (NEDGE_HALF / 16 + 255) / 256;   // 157
    prep_edges<<<eblocks, 256>>>(in1, w1, 0);            // launch 0
    prep_edges<<<eblocks, 256>>>(in1, w1, NEDGE_HALF);   // launch 1
    prep_feat<<<128 + 79, 256>>>(features, w2, b1, b2, w3, b3);  // launch 2
    fused_kernel<<<GRID, THREADS, SMEM_BYTES>>>();               // launch 3 (ncu target)
    transpose_out<<<dim3(NGENES / 32, BATCH / 32), dim3(32, 8)>>>(out);  // launch 4
}

// round 15
// speedup vs baseline: 1.2014x; 1.2014x over previous
#include <cuda_runtime.h>
#include <cuda_fp16.h>

#define BATCH 128
#define NTF 1024
#define NGENES 20000
#define NQUADS (NGENES / 4)          // 5000 gene-quads per chunk
#define NEDGE1 (NGENES * 64)         // 1,280,000 layer-1 edges
#define CHUNK 64                     // batch elements per block
#define THREADS 768                  // 24 warps -> ~85 reg budget
#define GRID 148                     // one wave, 74 blocks per chunk
#define WARPS_PER_CHUNK 1776         // 74 blocks * 24 warps
#define SMEM_BYTES (NTF * CHUNK * 2) // 131072
#define TAIL_W (NQUADS - 2 * WARPS_PER_CHUNK)   // 1448

// device scratch
__device__ __half g_xTh[NTF * BATCH];       // transposed fp16 features
__device__ unsigned int g_off[NEDGE1];      // pre-scaled byte offsets (idx*128)
__device__ __half g_w1h[NEDGE1];            // fp16 layer-1 weights
__device__ uint4  g_tail[NGENES * 4];       // 64B/gene packed tail
__device__ __half g_yTh[NGENES * BATCH];    // gene-major fp16 output

__device__ __forceinline__ unsigned int packh2(float a, float b) {
    const __half2 h = __float22half2_rn(make_float2(a, b));
    return *reinterpret_cast<const unsigned int*>(&h);
}

// ---- prep 1: offset + w1h tables, 8 edges/thread, full range, 625 blocks ----
__global__ void prep_edges(const int* __restrict__ in1,
                           const float* __restrict__ w1) {
    const int e = (blockIdx.x * 256 + threadIdx.x) * 8;
    const int4 i0 = __ldg((const int4*)(in1 + e));
    const int4 i1 = __ldg((const int4*)(in1 + e) + 1);
    const float4 a0 = __ldg((const float4*)(w1 + e));
    const float4 a1 = __ldg((const float4*)(w1 + e) + 1);
    uint4* od = (uint4*)(g_off + e);
    od[0] = make_uint4((unsigned)i0.x << 7, (unsigned)i0.y << 7,
                       (unsigned)i0.z << 7, (unsigned)i0.w << 7);
    od[1] = make_uint4((unsigned)i1.x << 7, (unsigned)i1.y << 7,
                       (unsigned)i1.z << 7, (unsigned)i1.w << 7);
    uint4 wv;
    wv.x = packh2(a0.x, a0.y); wv.y = packh2(a0.z, a0.w);
    wv.z = packh2(a1.x, a1.y); wv.w = packh2(a1.z, a1.w);
    *(uint4*)(g_w1h + e) = wv;
}

// ---- prep 2: feature transpose -> fp16, 128 blocks ----
__global__ void prep_feat(const float* __restrict__ f) {
    __shared__ float tile[32][33];
    const int tx = threadIdx.x & 31, ty = threadIdx.x >> 5;
    const int t0 = (blockIdx.x & 31) * 32;   // TF base
    const int b0 = (blockIdx.x >> 5) * 32;   // batch base
#pragma unroll
    for (int j = 0; j < 32; j += 8)
        tile[ty + j][tx] = f[(b0 + ty + j) * NTF + t0 + tx];
    __syncthreads();
#pragma unroll
    for (int j = 0; j < 32; j += 8)
        g_xTh[(t0 + ty + j) * BATCH + b0 + tx] = __float2half(tile[tx][ty + j]);
}

// ---- prep 3: tail structs, one gene/thread, 79 blocks ----
__global__ void prep_tail(const float* __restrict__ w2,
                          const float* __restrict__ b1,
                          const float* __restrict__ b2,
                          const float* __restrict__ w3,
                          const float* __restrict__ b3) {
    const int g = blockIdx.x * 256 + threadIdx.x;
    if (g < NGENES) {
        const float4 q0 = __ldg((const float4*)(w2 + g * 16));
        const float4 q1 = __ldg((const float4*)(w2 + g * 16) + 1);
        const float4 q2 = __ldg((const float4*)(w2 + g * 16) + 2);
        const float4 q3 = __ldg((const float4*)(w2 + g * 16) + 3);
        const float4 b1q = __ldg((const float4*)(b1 + g * 4));
        const float4 b2q = __ldg((const float4*)(b2 + g * 4));
        const float4 w3q = __ldg((const float4*)(w3 + g * 4));
        const float  b3s = __ldg(b3 + g);
        uint4 u0, u1, u2, u3;
        u0.x = packh2(q0.x, q0.y); u0.y = packh2(q0.z, q0.w);
        u0.z = packh2(q1.x, q1.y); u0.w = packh2(q1.z, q1.w);
        u1.x = packh2(q2.x, q2.y); u1.y = packh2(q2.z, q2.w);
        u1.z = packh2(q3.x, q3.y); u1.w = packh2(q3.z, q3.w);
        u2.x = packh2(b1q.x, b1q.y); u2.y = packh2(b1q.z, b1q.w);
        u2.z = packh2(b2q.x, b2q.y); u2.w = packh2(b2q.z, b2q.w);
        u3.x = packh2(w3q.x, w3q.y); u3.y = packh2(w3q.z, w3q.w);
        u3.z = __float_as_uint(b3s);  u3.w = 0u;
        uint4* dst = g_tail + (size_t)g * 4;
        dst[0] = u0; dst[1] = u1; dst[2] = u2; dst[3] = u3;
    }
}

// g_yTh [NGENES][BATCH] fp16 -> out [BATCH][NGENES] fp32
__global__ void transpose_out(float* __restrict__ out) {
    __shared__ float tile[32][33];
    const int tx = threadIdx.x, ty = threadIdx.y;
    const int g0 = blockIdx.x * 32;
    const int b0 = blockIdx.y * 32;
#pragma unroll
    for (int j = 0; j < 32; j += 8)
        tile[ty + j][tx] = __half2float(g_yTh[(size_t)(g0 + ty + j) * BATCH + b0 + tx]);
    __syncthreads();
#pragma unroll
    for (int j = 0; j < 32; j += 8)
        out[(size_t)(b0 + ty + j) * NGENES + g0 + tx] = tile[tx][ty + j];
}

__device__ __forceinline__ __half2 u2h(unsigned int u) {
    return *reinterpret_cast<__half2*>(&u);
}
__device__ __forceinline__ float tanh_mufu(float x) {
    float y;
    asm("tanh.approx.f32 %0, %1;" : "=f"(y) : "f"(x));
    return y;
}
__device__ __forceinline__ __half2 tanh_h2f(float2 a) {
    __half2 h = __float22half2_rn(a);
    unsigned int u = *reinterpret_cast<unsigned int*>(&h), r;
    asm("tanh.approx.f16x2 %0, %1;" : "=r"(r) : "r"(u));
    return u2h(r);
}

// 4 edges: LDS.128 row gathers (8 batches/lane), fp16 chain into acc[4]
__device__ __forceinline__ void group8(const char* fb, uint4 o,
                                       unsigned int wlo, unsigned int whi,
                                       __half2 acc[4], bool init) {
    const uint4 x0 = *(const uint4*)(fb + o.x);
    const uint4 x1 = *(const uint4*)(fb + o.y);
    const uint4 x2 = *(const uint4*)(fb + o.z);
    const uint4 x3 = *(const uint4*)(fb + o.w);
    const __half2 w0 = __low2half2(u2h(wlo));
    const __half2 w1 = __high2half2(u2h(wlo));
    const __half2 w2 = __low2half2(u2h(whi));
    const __half2 w3 = __high2half2(u2h(whi));
    const unsigned int* p0 = (const unsigned int*)&x0;
    const unsigned int* p1 = (const unsigned int*)&x1;
    const unsigned int* p2 = (const unsigned int*)&x2;
    const unsigned int* p3 = (const unsigned int*)&x3;
#pragma unroll
    for (int j = 0; j < 4; j++) {
        __half2 a = init ? __hmul2(w0, u2h(p0[j]))
                         : __hfma2(w0, u2h(p0[j]), acc[j]);
        a = __hfma2(w1, u2h(p1[j]), a);
        a = __hfma2(w2, u2h(p2[j]), a);
        a = __hfma2(w3, u2h(p3[j]), a);
        acc[j] = a;
    }
}

// layer-2 node (fp16 MAC) + fp32 tanh + fp32 layer-3 accumulate (8 batches)
__device__ __forceinline__ void l23_node8(const __half2* h1, unsigned int wlo,
                                          unsigned int whi, float b2o, float w3o,
                                          float* y) {
    const __half2 bb = __float2half2_rn(b2o);
    const __half2 q0 = __low2half2(u2h(wlo)),  q1 = __high2half2(u2h(wlo));
    const __half2 q2 = __low2half2(u2h(whi)),  q3 = __high2half2(u2h(whi));
#pragma unroll
    for (int j = 0; j < 4; j++) {
        __half2 s = bb;
        s = __hfma2(q0, h1[0 * 4 + j], s);
        s = __hfma2(q1, h1[1 * 4 + j], s);
        s = __hfma2(q2, h1[2 * 4 + j], s);
        s = __hfma2(q3, h1[3 * 4 + j], s);
        const float2 f = __half22float2(s);
        y[2 * j]     = fmaf(w3o, tanh_mufu(f.x), y[2 * j]);
        y[2 * j + 1] = fmaf(w3o, tanh_mufu(f.y), y[2 * j + 1]);
    }
}

// one gene-quad per warp: 4 genes x 8-batch lanes; metadata pipelined
__device__ __forceinline__ void compute_quad(const char* fb, int quad,
                                             int b0, int lane) {
    const int g = quad * 4 + (lane >> 3);
    const uint4* op = (const uint4*)(g_off + (size_t)g * 64);   // 16 uint4
    const uint4* wp = (const uint4*)(g_w1h + (size_t)g * 64);   // 8 uint4
    const uint4* tp = g_tail + (size_t)g * 4;

    // hoist whole tail: drains under layer 1 (reg budget allows at 768 thr)
    const uint4 u0 = __ldg(tp + 0);
    const uint4 u1 = __ldg(tp + 1);
    const uint4 u2 = __ldg(tp + 2);
    const uint4 u3 = __ldg(tp + 3);
    const float2 b1a = __half22float2(u2h(u2.x));
    const float2 b1b = __half22float2(u2h(u2.y));
    const float bn[4] = {b1a.x, b1a.y, b1b.x, b1b.y};

    // software pipeline: first half of node 0 pre-loaded
    uint4 oA = __ldg(op + 0);
    uint4 oB = __ldg(op + 1);
    uint4 wv = __ldg(wp + 0);

    __half2 h1[16];   // [node][4 x half2] = 8 batches per node
#pragma unroll
    for (int n = 0; n < 4; n++) {
        // second half of current node
        const uint4 oC  = __ldg(op + 4 * n + 2);
        const uint4 oD  = __ldg(op + 4 * n + 3);
        const uint4 wv2 = __ldg(wp + 2 * n + 1);
        __half2 a0[4], a1[4];
        group8(fb, oA, wv.x, wv.y, a0, true);
        group8(fb, oB, wv.z, wv.w, a1, true);
        // prefetch next node's first half while second half computes
        uint4 oA2, oB2, wvn;
        if (n < 3) {
            oA2 = __ldg(op + 4 * n + 4);
            oB2 = __ldg(op + 4 * n + 5);
            wvn = __ldg(wp + 2 * n + 2);
        }
        group8(fb, oC, wv2.x, wv2.y, a0, false);
        group8(fb, oD, wv2.z, wv2.w, a1, false);
#pragma unroll
        for (int j = 0; j < 4; j++) {
            const __half2 s = __hadd2(a0[j], a1[j]);
            const float2 f = __half22float2(s);
            h1[4 * n + j] = tanh_h2f(make_float2(f.x + bn[n], f.y + bn[n]));
        }
        if (n < 3) { oA = oA2; oB = oB2; wv = wvn; }
    }

    const float2 b2a = __half22float2(u2h(u2.z));
    const float2 b2b = __half22float2(u2h(u2.w));
    const float2 w3a = __half22float2(u2h(u3.x));
    const float2 w3b = __half22float2(u2h(u3.y));
    const float  yb  = __uint_as_float(u3.z);
    float y[8];
#pragma unroll
    for (int i = 0; i < 8; i++) y[i] = yb;
    l23_node8(h1, u0.x, u0.y, b2a.x, w3a.x, y);
    l23_node8(h1, u0.z, u0.w, b2a.y, w3a.y, y);
    l23_node8(h1, u1.x, u1.y, b2b.x, w3b.x, y);
    l23_node8(h1, u1.z, u1.w, b2b.y, w3b.y, y);

    uint4 out;
    out.x = packh2(y[0], y[1]); out.y = packh2(y[2], y[3]);
    out.z = packh2(y[4], y[5]); out.w = packh2(y[6], y[7]);
    *(uint4*)&g_yTh[(size_t)g * BATCH + b0 + (lane & 7) * 8] = out;
}

__global__ void __launch_bounds__(THREADS, 1) fused_kernel() {
    extern __shared__ unsigned int xs[];   // [NTF][32] uint -> 128B fp16 rows
    const int tid = threadIdx.x;
    const int chunk = blockIdx.x & 1;      // 148 blocks -> 74 per chunk
    const int b0 = chunk * CHUNK;

    // fill feature slice (rows of 64 fp16 = 8 uint4)
    {
        const uint4* src = (const uint4*)g_xTh;  // global row = 16 uint4
        uint4* dst = (uint4*)xs;
        for (int i = tid; i < NTF * 8; i += THREADS) {
            const int t = i >> 3, c = i & 7;
            dst[i] = src[t * 16 + chunk * 8 + c];
        }
    }
    __syncthreads();

    const int lane = tid & 31;
    const char* fb = (const char*)xs + (lane & 7) * 16;  // lane's 8-batch column
    const int w = (blockIdx.x >> 1) * 24 + (tid >> 5);   // 0..1775 in chunk

    compute_quad(fb, w, b0, lane);
    compute_quad(fb, WARPS_PER_CHUNK + w, b0, lane);
    if (w < TAIL_W)
        compute_quad(fb, 2 * WARPS_PER_CHUNK + w, b0, lane);
}

extern "C" void kernel_launch(void* const* d_in, const int* in_sizes, int n_in,
                              void* d_out, int out_size) {
    const float* features = (const float*)d_in[0];
    const float* w1 = (const float*)d_in[1];
    const float* b1 = (const float*)d_in[2];
    const float* w2 = (const float*)d_in[3];
    const float* b2 = (const float*)d_in[4];
    const float* w3 = (const float*)d_in[5];
    const float* b3 = (const float*)d_in[6];
    const int* in1 = (const int*)d_in[8];
    float* out = (float*)d_out;

    cudaFuncSetAttribute(fused_kernel,
                         cudaFuncAttributeMaxDynamicSharedMemorySize, SMEM_BYTES);

    prep_edges<<<625, 256>>>(in1, w1);                   // launch 0
    prep_feat<<<128, 256>>>(features);                   // launch 1
    prep_tail<<<79, 256>>>(w2, b1, b2, w3, b3);          // launch 2
    fused_kernel<<<GRID, THREADS, SMEM_BYTES>>>();       // launch 3 (ncu target)
    transpose_out<<<dim3(NGENES / 32, BATCH / 32), dim3(32, 8)>>>(out);  // launch 4
}

// round 16
// speedup vs baseline: 1.2384x; 1.0308x over previous
#include <cuda_runtime.h>
#include <cuda_fp16.h>

#define BATCH 128
#define NTF 1024
#define NGENES 20000
#define NQUADS (NGENES / 4)          // 5000 gene-quads per chunk
#define NEDGE1 (NGENES * 64)         // 1,280,000 layer-1 edges
#define CHUNK 64                     // batch elements per block
#define THREADS 768                  // 24 warps
#define GRID 148                     // one wave, 74 blocks per chunk
#define WARPS_PER_CHUNK 1776         // 74 blocks * 24 warps
#define TAIL_W (NQUADS - 2 * WARPS_PER_CHUNK)   // 1448

#define FEAT_BYTES (NTF * CHUNK * 2)             // 131072
#define META_STRIDE 1536                         // 1024B idx + 512B w1h
#define META_BYTES (24 * 2 * META_STRIDE)        // 73728
#define SMEM_TOTAL (FEAT_BYTES + META_BYTES)     // 204800

// device scratch
__device__ __half g_xTh[NTF * BATCH];       // transposed fp16 features
__device__ __half g_w1h[NEDGE1];            // fp16 layer-1 weights
__device__ uint4  g_tail[NGENES * 4];       // 64B/gene packed tail
__device__ __half g_yTh[NGENES * BATCH];    // gene-major fp16 output

__device__ __forceinline__ unsigned int packh2(float a, float b) {
    const __half2 h = __float22half2_rn(make_float2(a, b));
    return *reinterpret_cast<const unsigned int*>(&h);
}

// ---- prep 1: w1 fp32 -> fp16, 8 edges/thread, 625 blocks ----
__global__ void prep_w1(const float* __restrict__ w1) {
    const int e = (blockIdx.x * 256 + threadIdx.x) * 8;
    const float4 a0 = __ldg((const float4*)(w1 + e));
    const float4 a1 = __ldg((const float4*)(w1 + e) + 1);
    uint4 wv;
    wv.x = packh2(a0.x, a0.y); wv.y = packh2(a0.z, a0.w);
    wv.z = packh2(a1.x, a1.y); wv.w = packh2(a1.z, a1.w);
    *(uint4*)(g_w1h + e) = wv;
}

// ---- prep 2: feature transpose -> fp16, 128 blocks ----
__global__ void prep_feat(const float* __restrict__ f) {
    __shared__ float tile[32][33];
    const int tx = threadIdx.x & 31, ty = threadIdx.x >> 5;
    const int t0 = (blockIdx.x & 31) * 32;   // TF base
    const int b0 = (blockIdx.x >> 5) * 32;   // batch base
#pragma unroll
    for (int j = 0; j < 32; j += 8)
        tile[ty + j][tx] = f[(b0 + ty + j) * NTF + t0 + tx];
    __syncthreads();
#pragma unroll
    for (int j = 0; j < 32; j += 8)
        g_xTh[(t0 + ty + j) * BATCH + b0 + tx] = __float2half(tile[tx][ty + j]);
}

// ---- prep 3: tail structs, one gene/thread, 79 blocks ----
__global__ void prep_tail(const float* __restrict__ w2,
                          const float* __restrict__ b1,
                          const float* __restrict__ b2,
                          const float* __restrict__ w3,
                          const float* __restrict__ b3) {
    const int g = blockIdx.x * 256 + threadIdx.x;
    if (g < NGENES) {
        const float4 q0 = __ldg((const float4*)(w2 + g * 16));
        const float4 q1 = __ldg((const float4*)(w2 + g * 16) + 1);
        const float4 q2 = __ldg((const float4*)(w2 + g * 16) + 2);
        const float4 q3 = __ldg((const float4*)(w2 + g * 16) + 3);
        const float4 b1q = __ldg((const float4*)(b1 + g * 4));
        const float4 b2q = __ldg((const float4*)(b2 + g * 4));
        const float4 w3q = __ldg((const float4*)(w3 + g * 4));
        const float  b3s = __ldg(b3 + g);
        uint4 u0, u1, u2, u3;
        u0.x = packh2(q0.x, q0.y); u0.y = packh2(q0.z, q0.w);
        u0.z = packh2(q1.x, q1.y); u0.w = packh2(q1.z, q1.w);
        u1.x = packh2(q2.x, q2.y); u1.y = packh2(q2.z, q2.w);
        u1.z = packh2(q3.x, q3.y); u1.w = packh2(q3.z, q3.w);
        u2.x = packh2(b1q.x, b1q.y); u2.y = packh2(b1q.z, b1q.w);
        u2.z = packh2(b2q.x, b2q.y); u2.w = packh2(b2q.z, b2q.w);
        u3.x = packh2(w3q.x, w3q.y); u3.y = packh2(w3q.z, w3q.w);
        u3.z = __float_as_uint(b3s);  u3.w = 0u;
        uint4* dst = g_tail + (size_t)g * 4;
        dst[0] = u0; dst[1] = u1; dst[2] = u2; dst[3] = u3;
    }
}

// g_yTh [NGENES][BATCH] fp16 -> out [BATCH][NGENES] fp32
__global__ void transpose_out(float* __restrict__ out) {
    __shared__ float tile[32][33];
    const int tx = threadIdx.x, ty = threadIdx.y;
    const int g0 = blockIdx.x * 32;
    const int b0 = blockIdx.y * 32;
#pragma unroll
    for (int j = 0; j < 32; j += 8)
        tile[ty + j][tx] = __half2float(g_yTh[(size_t)(g0 + ty + j) * BATCH + b0 + tx]);
    __syncthreads();
#pragma unroll
    for (int j = 0; j < 32; j += 8)
        out[(size_t)(b0 + ty + j) * NGENES + g0 + tx] = tile[tx][ty + j];
}

__device__ __forceinline__ __half2 u2h(unsigned int u) {
    return *reinterpret_cast<__half2*>(&u);
}
__device__ __forceinline__ float tanh_mufu(float x) {
    float y;
    asm("tanh.approx.f32 %0, %1;" : "=f"(y) : "f"(x));
    return y;
}
__device__ __forceinline__ __half2 tanh_h2f(float2 a) {
    __half2 h = __float22half2_rn(a);
    unsigned int u = *reinterpret_cast<unsigned int*>(&h), r;
    asm("tanh.approx.f16x2 %0, %1;" : "=r"(r) : "r"(u));
    return u2h(r);
}
__device__ __forceinline__ void cp16(unsigned int saddr, const void* gaddr) {
    asm volatile("cp.async.ca.shared.global [%0], [%1], 16;"
                 :: "r"(saddr), "l"(gaddr));
}

// stage one quad's metadata: in1 (1024B) + w1h (512B), swizzled so that the
// 4 gene-groups' simultaneous reads are 64B-contiguous (conflict-free)
__device__ __forceinline__ void prefetch_quad(unsigned int dst, int quad,
                                              int lane, const int* in1) {
    const char* si = (const char*)in1 + (size_t)quad * 1024;
    const char* sw = (const char*)g_w1h + (size_t)quad * 512;
    const int s0 = lane, s1 = lane + 32;
    const unsigned int d0 = (unsigned)(((s0 & 15) << 2) + (s0 >> 4)) << 4;
    const unsigned int d1 = (unsigned)(((s1 & 15) << 2) + (s1 >> 4)) << 4;
    cp16(dst + d0, si + s0 * 16);
    cp16(dst + d1, si + s1 * 16);
    const unsigned int dw = (unsigned)(((lane & 7) << 2) + (lane >> 3)) << 4;
    cp16(dst + 1024 + dw, sw + lane * 16);
    asm volatile("cp.async.commit_group;" ::: "memory");
}

// 4 edges: LDS.128 row gathers (8 batches/lane), fp16 chain into acc[4]
__device__ __forceinline__ void group8i(const char* fb, int4 iv,
                                        unsigned int wlo, unsigned int whi,
                                        __half2 acc[4], bool init) {
    const uint4 x0 = *(const uint4*)(fb + ((unsigned)iv.x << 7));
    const uint4 x1 = *(const uint4*)(fb + ((unsigned)iv.y << 7));
    const uint4 x2 = *(const uint4*)(fb + ((unsigned)iv.z << 7));
    const uint4 x3 = *(const uint4*)(fb + ((unsigned)iv.w << 7));
    const __half2 w0 = __low2half2(u2h(wlo));
    const __half2 w1 = __high2half2(u2h(wlo));
    const __half2 w2 = __low2half2(u2h(whi));
    const __half2 w3 = __high2half2(u2h(whi));
    const unsigned int* p0 = (const unsigned int*)&x0;
    const unsigned int* p1 = (const unsigned int*)&x1;
    const unsigned int* p2 = (const unsigned int*)&x2;
    const unsigned int* p3 = (const unsigned int*)&x3;
#pragma unroll
    for (int j = 0; j < 4; j++) {
        __half2 a = init ? __hmul2(w0, u2h(p0[j]))
                         : __hfma2(w0, u2h(p0[j]), acc[j]);
        a = __hfma2(w1, u2h(p1[j]), a);
        a = __hfma2(w2, u2h(p2[j]), a);
        a = __hfma2(w3, u2h(p3[j]), a);
        acc[j] = a;
    }
}

// layer-2 node (fp16 MAC) + fp32 tanh + fp32 layer-3 accumulate (8 batches)
__device__ __forceinline__ void l23_node8(const __half2* h1, unsigned int wlo,
                                          unsigned int whi, float b2o, float w3o,
                                          float* y) {
    const __half2 bb = __float2half2_rn(b2o);
    const __half2 q0 = __low2half2(u2h(wlo)),  q1 = __high2half2(u2h(wlo));
    const __half2 q2 = __low2half2(u2h(whi)),  q3 = __high2half2(u2h(whi));
#pragma unroll
    for (int j = 0; j < 4; j++) {
        __half2 s = bb;
        s = __hfma2(q0, h1[0 * 4 + j], s);
        s = __hfma2(q1, h1[1 * 4 + j], s);
        s = __hfma2(q2, h1[2 * 4 + j], s);
        s = __hfma2(q3, h1[3 * 4 + j], s);
        const float2 f = __half22float2(s);
        y[2 * j]     = fmaf(w3o, tanh_mufu(f.x), y[2 * j]);
        y[2 * j + 1] = fmaf(w3o, tanh_mufu(f.y), y[2 * j + 1]);
    }
}

// one gene-quad per warp: metadata from staged smem (swizzled layout)
__device__ __forceinline__ void compute_quad(const char* mbuf, const char* fb,
                                             int quad, int b0, int lane) {
    const int gl = lane >> 3;
    const int g = quad * 4 + gl;
    const uint4* tp = g_tail + (size_t)g * 4;

    const uint4 u0 = __ldg(tp + 0);
    const uint4 u1 = __ldg(tp + 1);
    const uint4 u2 = __ldg(tp + 2);
    const uint4 u3 = __ldg(tp + 3);
    const float2 b1a = __half22float2(u2h(u2.x));
    const float2 b1b = __half22float2(u2h(u2.y));
    const float bn[4] = {b1a.x, b1a.y, b1b.x, b1b.y};

    __half2 h1[16];   // [node][4 x half2] = 8 batches per node
#pragma unroll
    for (int n = 0; n < 4; n++) {
        // swizzled granules: idx granule r at mbuf + (r*4+gl)*16
        const int4 iA = *(const int4*)(mbuf + (((4 * n + 0) << 2) + gl) * 16);
        const int4 iB = *(const int4*)(mbuf + (((4 * n + 1) << 2) + gl) * 16);
        const int4 iC = *(const int4*)(mbuf + (((4 * n + 2) << 2) + gl) * 16);
        const int4 iD = *(const int4*)(mbuf + (((4 * n + 3) << 2) + gl) * 16);
        const uint4 wa = *(const uint4*)(mbuf + 1024 + (((2 * n) << 2) + gl) * 16);
        const uint4 wb = *(const uint4*)(mbuf + 1024 + (((2 * n + 1) << 2) + gl) * 16);
        __half2 a0[4], a1[4];
        group8i(fb, iA, wa.x, wa.y, a0, true);
        group8i(fb, iB, wa.z, wa.w, a1, true);
        group8i(fb, iC, wb.x, wb.y, a0, false);
        group8i(fb, iD, wb.z, wb.w, a1, false);
#pragma unroll
        for (int j = 0; j < 4; j++) {
            const __half2 s = __hadd2(a0[j], a1[j]);
            const float2 f = __half22float2(s);
            h1[4 * n + j] = tanh_h2f(make_float2(f.x + bn[n], f.y + bn[n]));
        }
    }

    const float2 b2a = __half22float2(u2h(u2.z));
    const float2 b2b = __half22float2(u2h(u2.w));
    const float2 w3a = __half22float2(u2h(u3.x));
    const float2 w3b = __half22float2(u2h(u3.y));
    const float  yb  = __uint_as_float(u3.z);
    float y[8];
#pragma unroll
    for (int i = 0; i < 8; i++) y[i] = yb;
    l23_node8(h1, u0.x, u0.y, b2a.x, w3a.x, y);
    l23_node8(h1, u0.z, u0.w, b2a.y, w3a.y, y);
    l23_node8(h1, u1.x, u1.y, b2b.x, w3b.x, y);
    l23_node8(h1, u1.z, u1.w, b2b.y, w3b.y, y);

    uint4 outv;
    outv.x = packh2(y[0], y[1]); outv.y = packh2(y[2], y[3]);
    outv.z = packh2(y[4], y[5]); outv.w = packh2(y[6], y[7]);
    *(uint4*)&g_yTh[(size_t)g * BATCH + b0 + (lane & 7) * 8] = outv;
}

__global__ void __launch_bounds__(THREADS, 1) fused_kernel(
    const int* __restrict__ in1)
{
    extern __shared__ char smem_raw[];
    const int tid = threadIdx.x;
    const int chunk = blockIdx.x & 1;      // 148 blocks -> 74 per chunk
    const int b0 = chunk * CHUNK;

    // fill feature slice (rows of 64 fp16 = 8 uint4)
    {
        const uint4* src = (const uint4*)g_xTh;  // global row = 16 uint4
        uint4* dst = (uint4*)smem_raw;
        for (int i = tid; i < NTF * 8; i += THREADS) {
            const int t = i >> 3, c = i & 7;
            dst[i] = src[t * 16 + chunk * 8 + c];
        }
    }
    __syncthreads();

    const int lane = tid & 31;
    const int warp = tid >> 5;
    const char* fb = smem_raw + (lane & 7) * 16;   // lane's 8-batch column
    char* mymeta = smem_raw + FEAT_BYTES + warp * (2 * META_STRIDE);
    const unsigned int mymeta_s =
        (unsigned int)__cvta_generic_to_shared(mymeta);
    const int w = (blockIdx.x >> 1) * 24 + warp;   // 0..1775 in chunk
    const int niter = (w < TAIL_W) ? 3 : 2;

    prefetch_quad(mymeta_s, w, lane, in1);

    for (int k = 0; k < niter; k++) {
        asm volatile("cp.async.wait_group 0;" ::: "memory");
        __syncwarp();
        if (k + 1 < niter)
            prefetch_quad(mymeta_s + ((k + 1) & 1) * META_STRIDE,
                          (k + 1) * WARPS_PER_CHUNK + w, lane, in1);
        compute_quad(mymeta + (k & 1) * META_STRIDE, fb,
                     k * WARPS_PER_CHUNK + w, b0, lane);
    }
}

extern "C" void kernel_launch(void* const* d_in, const int* in_sizes, int n_in,
                              void* d_out, int out_size) {
    const float* features = (const float*)d_in[0];
    const float* w1 = (const float*)d_in[1];
    const float* b1 = (const float*)d_in[2];
    const float* w2 = (const float*)d_in[3];
    const float* b2 = (const float*)d_in[4];
    const float* w3 = (const float*)d_in[5];
    const float* b3 = (const float*)d_in[6];
    const int* in1 = (const int*)d_in[8];
    float* out = (float*)d_out;

    cudaFuncSetAttribute(fused_kernel,
                         cudaFuncAttributeMaxDynamicSharedMemorySize, SMEM_TOTAL);

    prep_w1<<<625, 256>>>(w1);                           // launch 0
    prep_feat<<<128, 256>>>(features);                   // launch 1
    prep_tail<<<79, 256>>>(w2, b1, b2, w3, b3);          // launch 2
    fused_kernel<<<GRID, THREADS, SMEM_TOTAL>>>(in1);    // launch 3 (ncu target)
    transpose_out<<<dim3(NGENES / 32, BATCH / 32), dim3(32, 8)>>>(out);  // launch 4
}

// round 17
// speedup vs baseline: 1.3047x; 1.0535x over previous
#include <cuda_runtime.h>
#include <cuda_fp16.h>

#define BATCH 128
#define NTF 1024
#define NGENES 20000
#define NQUADS (NGENES / 4)          // 5000 gene-quads per chunk
#define CHUNK 64                     // batch elements per block
#define THREADS 768                  // 24 warps
#define GRID 148                     // one wave, 74 blocks per chunk
#define WARPS_PER_CHUNK 1776         // 74 blocks * 24 warps
#define TAIL_W (NQUADS - 2 * WARPS_PER_CHUNK)   // 1448

#define FEAT_BYTES (NTF * CHUNK * 2)             // 131072
#define META_STRIDE 2048                         // 1024B idx + 1024B w1 fp32
#define META_BYTES (24 * 2 * META_STRIDE)        // 98304
#define SMEM_TOTAL (FEAT_BYTES + META_BYTES)     // 229376

// device scratch
__device__ __half g_xTh[NTF * BATCH];       // transposed fp16 features
__device__ uint4  g_tail[NGENES * 4];       // 64B/gene packed tail
__device__ __half g_yTh[NGENES * BATCH];    // gene-major fp16 output

__device__ __forceinline__ unsigned int packh2(float a, float b) {
    const __half2 h = __float22half2_rn(make_float2(a, b));
    return *reinterpret_cast<const unsigned int*>(&h);
}

// ---- prep 1: feature transpose -> fp16, 128 blocks ----
__global__ void prep_feat(const float* __restrict__ f) {
    __shared__ float tile[32][33];
    const int tx = threadIdx.x & 31, ty = threadIdx.x >> 5;
    const int t0 = (blockIdx.x & 31) * 32;   // TF base
    const int b0 = (blockIdx.x >> 5) * 32;   // batch base
#pragma unroll
    for (int j = 0; j < 32; j += 8)
        tile[ty + j][tx] = f[(b0 + ty + j) * NTF + t0 + tx];
    __syncthreads();
#pragma unroll
    for (int j = 0; j < 32; j += 8)
        g_xTh[(t0 + ty + j) * BATCH + b0 + tx] = __float2half(tile[tx][ty + j]);
}

// ---- prep 2: tail structs, one gene/thread, 79 blocks ----
__global__ void prep_tail(const float* __restrict__ w2,
                          const float* __restrict__ b1,
                          const float* __restrict__ b2,
                          const float* __restrict__ w3,
                          const float* __restrict__ b3) {
    const int g = blockIdx.x * 256 + threadIdx.x;
    if (g < NGENES) {
        const float4 q0 = __ldg((const float4*)(w2 + g * 16));
        const float4 q1 = __ldg((const float4*)(w2 + g * 16) + 1);
        const float4 q2 = __ldg((const float4*)(w2 + g * 16) + 2);
        const float4 q3 = __ldg((const float4*)(w2 + g * 16) + 3);
        const float4 b1q = __ldg((const float4*)(b1 + g * 4));
        const float4 b2q = __ldg((const float4*)(b2 + g * 4));
        const float4 w3q = __ldg((const float4*)(w3 + g * 4));
        const float  b3s = __ldg(b3 + g);
        uint4 u0, u1, u2, u3;
        u0.x = packh2(q0.x, q0.y); u0.y = packh2(q0.z, q0.w);
        u0.z = packh2(q1.x, q1.y); u0.w = packh2(q1.z, q1.w);
        u1.x = packh2(q2.x, q2.y); u1.y = packh2(q2.z, q2.w);
        u1.z = packh2(q3.x, q3.y); u1.w = packh2(q3.z, q3.w);
        u2.x = packh2(b1q.x, b1q.y); u2.y = packh2(b1q.z, b1q.w);
        u2.z = packh2(b2q.x, b2q.y); u2.w = packh2(b2q.z, b2q.w);
        u3.x = packh2(w3q.x, w3q.y); u3.y = packh2(w3q.z, w3q.w);
        u3.z = __float_as_uint(b3s);  u3.w = 0u;
        uint4* dst = g_tail + (size_t)g * 4;
        dst[0] = u0; dst[1] = u1; dst[2] = u2; dst[3] = u3;
    }
}

// g_yTh [NGENES][BATCH] fp16 -> out [BATCH][NGENES] fp32
__global__ void transpose_out(float* __restrict__ out) {
    __shared__ float tile[32][33];
    const int tx = threadIdx.x, ty = threadIdx.y;
    const int g0 = blockIdx.x * 32;
    const int b0 = blockIdx.y * 32;
#pragma unroll
    for (int j = 0; j < 32; j += 8)
        tile[ty + j][tx] = __half2float(g_yTh[(size_t)(g0 + ty + j) * BATCH + b0 + tx]);
    __syncthreads();
#pragma unroll
    for (int j = 0; j < 32; j += 8)
        out[(size_t)(b0 + ty + j) * NGENES + g0 + tx] = tile[tx][ty + j];
}

__device__ __forceinline__ __half2 u2h(unsigned int u) {
    return *reinterpret_cast<__half2*>(&u);
}
__device__ __forceinline__ float tanh_mufu(float x) {
    float y;
    asm("tanh.approx.f32 %0, %1;" : "=f"(y) : "f"(x));
    return y;
}
__device__ __forceinline__ __half2 tanh_h2f(float2 a) {
    __half2 h = __float22half2_rn(a);
    unsigned int u = *reinterpret_cast<unsigned int*>(&h), r;
    asm("tanh.approx.f16x2 %0, %1;" : "=r"(r) : "r"(u));
    return u2h(r);
}
__device__ __forceinline__ void cp16(unsigned int saddr, const void* gaddr) {
    asm volatile("cp.async.ca.shared.global [%0], [%1], 16;"
                 :: "r"(saddr), "l"(gaddr));
}

// stage one quad's metadata: in1 (1024B) + RAW fp32 w1 (1024B), both swizzled
// so the 4 gene-groups' simultaneous reads are 64B-contiguous (conflict-free)
__device__ __forceinline__ void prefetch_quad(unsigned int dst, int quad,
                                              int lane, const int* in1,
                                              const float* w1) {
    const char* si = (const char*)in1 + (size_t)quad * 1024;
    const char* sw = (const char*)w1 + (size_t)quad * 1024;
    const int s0 = lane, s1 = lane + 32;
    const unsigned int d0 = (unsigned)(((s0 & 15) << 2) + (s0 >> 4)) << 4;
    const unsigned int d1 = (unsigned)(((s1 & 15) << 2) + (s1 >> 4)) << 4;
    cp16(dst + d0, si + s0 * 16);
    cp16(dst + d1, si + s1 * 16);
    cp16(dst + 1024 + d0, sw + s0 * 16);
    cp16(dst + 1024 + d1, sw + s1 * 16);
    asm volatile("cp.async.commit_group;" ::: "memory");
}

// 4 edges: LDS.128 row gathers (8 batches/lane), fp16 chain into acc[4]
__device__ __forceinline__ void group8i(const char* fb, int4 iv,
                                        unsigned int wlo, unsigned int whi,
                                        __half2 acc[4], bool init) {
    const uint4 x0 = *(const uint4*)(fb + ((unsigned)iv.x << 7));
    const uint4 x1 = *(const uint4*)(fb + ((unsigned)iv.y << 7));
    const uint4 x2 = *(const uint4*)(fb + ((unsigned)iv.z << 7));
    const uint4 x3 = *(const uint4*)(fb + ((unsigned)iv.w << 7));
    const __half2 w0 = __low2half2(u2h(wlo));
    const __half2 w1 = __high2half2(u2h(wlo));
    const __half2 w2 = __low2half2(u2h(whi));
    const __half2 w3 = __high2half2(u2h(whi));
    const unsigned int* p0 = (const unsigned int*)&x0;
    const unsigned int* p1 = (const unsigned int*)&x1;
    const unsigned int* p2 = (const unsigned int*)&x2;
    const unsigned int* p3 = (const unsigned int*)&x3;
#pragma unroll
    for (int j = 0; j < 4; j++) {
        __half2 a = init ? __hmul2(w0, u2h(p0[j]))
                         : __hfma2(w0, u2h(p0[j]), acc[j]);
        a = __hfma2(w1, u2h(p1[j]), a);
        a = __hfma2(w2, u2h(p2[j]), a);
        a = __hfma2(w3, u2h(p3[j]), a);
        acc[j] = a;
    }
}

// layer-2 node (fp16 MAC) + fp32 tanh + fp32 layer-3 accumulate (8 batches)
__device__ __forceinline__ void l23_node8(const __half2* h1, unsigned int wlo,
                                          unsigned int whi, float b2o, float w3o,
                                          float* y) {
    const __half2 bb = __float2half2_rn(b2o);
    const __half2 q0 = __low2half2(u2h(wlo)),  q1 = __high2half2(u2h(wlo));
    const __half2 q2 = __low2half2(u2h(whi)),  q3 = __high2half2(u2h(whi));
#pragma unroll
    for (int j = 0; j < 4; j++) {
        __half2 s = bb;
        s = __hfma2(q0, h1[0 * 4 + j], s);
        s = __hfma2(q1, h1[1 * 4 + j], s);
        s = __hfma2(q2, h1[2 * 4 + j], s);
        s = __hfma2(q3, h1[3 * 4 + j], s);
        const float2 f = __half22float2(s);
        y[2 * j]     = fmaf(w3o, tanh_mufu(f.x), y[2 * j]);
        y[2 * j + 1] = fmaf(w3o, tanh_mufu(f.y), y[2 * j + 1]);
    }
}

// one gene-quad per warp: metadata from staged smem (swizzled layout);
// w1 converted fp32->fp16 on the fly (bit-identical to the old prep_w1)
__device__ __forceinline__ void compute_quad(const char* mbuf, const char* fb,
                                             int quad, int b0, int lane) {
    const int gl = lane >> 3;
    const int g = quad * 4 + gl;
    const uint4* tp = g_tail + (size_t)g * 4;

    const uint4 u0 = __ldg(tp + 0);
    const uint4 u1 = __ldg(tp + 1);
    const uint4 u2 = __ldg(tp + 2);
    const uint4 u3 = __ldg(tp + 3);
    const float2 b1a = __half22float2(u2h(u2.x));
    const float2 b1b = __half22float2(u2h(u2.y));
    const float bn[4] = {b1a.x, b1a.y, b1b.x, b1b.y};

    __half2 h1[16];   // [node][4 x half2] = 8 batches per node
#pragma unroll
    for (int n = 0; n < 4; n++) {
        // swizzled granules: granule r at mbuf + (r*4+gl)*16
        const int4 iA = *(const int4*)(mbuf + (((4 * n + 0) << 2) + gl) * 16);
        const int4 iB = *(const int4*)(mbuf + (((4 * n + 1) << 2) + gl) * 16);
        const int4 iC = *(const int4*)(mbuf + (((4 * n + 2) << 2) + gl) * 16);
        const int4 iD = *(const int4*)(mbuf + (((4 * n + 3) << 2) + gl) * 16);
        const char* wq = mbuf + 1024;
        __half2 a0[4], a1[4];
        {
            const float4 fA = *(const float4*)(wq + (((4 * n + 0) << 2) + gl) * 16);
            group8i(fb, iA, packh2(fA.x, fA.y), packh2(fA.z, fA.w), a0, true);
        }
        {
            const float4 fB = *(const float4*)(wq + (((4 * n + 1) << 2) + gl) * 16);
            group8i(fb, iB, packh2(fB.x, fB.y), packh2(fB.z, fB.w), a1, true);
        }
        {
            const float4 fC = *(const float4*)(wq + (((4 * n + 2) << 2) + gl) * 16);
            group8i(fb, iC, packh2(fC.x, fC.y), packh2(fC.z, fC.w), a0, false);
        }
        {
            const float4 fD = *(const float4*)(wq + (((4 * n + 3) << 2) + gl) * 16);
            group8i(fb, iD, packh2(fD.x, fD.y), packh2(fD.z, fD.w), a1, false);
        }
#pragma unroll
        for (int j = 0; j < 4; j++) {
            const __half2 s = __hadd2(a0[j], a1[j]);
            const float2 f = __half22float2(s);
            h1[4 * n + j] = tanh_h2f(make_float2(f.x + bn[n], f.y + bn[n]));
        }
    }

    const float2 b2a = __half22float2(u2h(u2.z));
    const float2 b2b = __half22float2(u2h(u2.w));
    const float2 w3a = __half22float2(u2h(u3.x));
    const float2 w3b = __half22float2(u2h(u3.y));
    const float  yb  = __uint_as_float(u3.z);
    float y[8];
#pragma unroll
    for (int i = 0; i < 8; i++) y[i] = yb;
    l23_node8(h1, u0.x, u0.y, b2a.x, w3a.x, y);
    l23_node8(h1, u0.z, u0.w, b2a.y, w3a.y, y);
    l23_node8(h1, u1.x, u1.y, b2b.x, w3b.x, y);
    l23_node8(h1, u1.z, u1.w, b2b.y, w3b.y, y);

    uint4 outv;
    outv.x = packh2(y[0], y[1]); outv.y = packh2(y[2], y[3]);
    outv.z = packh2(y[4], y[5]); outv.w = packh2(y[6], y[7]);
    *(uint4*)&g_yTh[(size_t)g * BATCH + b0 + (lane & 7) * 8] = outv;
}

__global__ void __launch_bounds__(THREADS, 1) fused_kernel(
    const int* __restrict__ in1, const float* __restrict__ w1)
{
    extern __shared__ char smem_raw[];
    const int tid = threadIdx.x;
    const int chunk = blockIdx.x & 1;      // 148 blocks -> 74 per chunk
    const int b0 = chunk * CHUNK;

    // fill feature slice (rows of 64 fp16 = 8 uint4)
    {
        const uint4* src = (const uint4*)g_xTh;  // global row = 16 uint4
        uint4* dst = (uint4*)smem_raw;
        for (int i = tid; i < NTF * 8; i += THREADS) {
            const int t = i >> 3, c = i & 7;
            dst[i] = src[t * 16 + chunk * 8 + c];
        }
    }
    __syncthreads();

    const int lane = tid & 31;
    const int warp = tid >> 5;
    const char* fb = smem_raw + (lane & 7) * 16;   // lane's 8-batch column
    char* mymeta = smem_raw + FEAT_BYTES + warp * (2 * META_STRIDE);
    const unsigned int mymeta_s =
        (unsigned int)__cvta_generic_to_shared(mymeta);
    const int w = (blockIdx.x >> 1) * 24 + warp;   // 0..1775 in chunk
    const int niter = (w < TAIL_W) ? 3 : 2;

    prefetch_quad(mymeta_s, w, lane, in1, w1);

    for (int k = 0; k < niter; k++) {
        asm volatile("cp.async.wait_group 0;" ::: "memory");
        __syncwarp();
        if (k + 1 < niter)
            prefetch_quad(mymeta_s + ((k + 1) & 1) * META_STRIDE,
                          (k + 1) * WARPS_PER_CHUNK + w, lane, in1, w1);
        compute_quad(mymeta + (k & 1) * META_STRIDE, fb,
                     k * WARPS_PER_CHUNK + w, b0, lane);
    }
}

extern "C" void kernel_launch(void* const* d_in, const int* in_sizes, int n_in,
                              void* d_out, int out_size) {
    const float* features = (const float*)d_in[0];
    const float* w1 = (const float*)d_in[1];
    const float* b1 = (const float*)d_in[2];
    const float* w2 = (const float*)d_in[3];
    const float* b2 = (const float*)d_in[4];
    const float* w3 = (const float*)d_in[5];
    const float* b3 = (const float*)d_in[6];
    const int* in1 = (const int*)d_in[8];
    float* out = (float*)d_out;

    cudaFuncSetAttribute(fused_kernel,
                         cudaFuncAttributeMaxDynamicSharedMemorySize, SMEM_TOTAL);

    prep_feat<<<128, 256>>>(features);                       // launch 0
    prep_tail<<<79, 256>>>(w2, b1, b2, w3, b3);              // launch 1
    fused_kernel<<<GRID, THREADS, SMEM_TOTAL>>>(in1, w1);    // launch 2
    transpose_out<<<dim3(NGENES / 32, BATCH / 32), dim3(32, 8)>>>(out);  // launch 3 (ncu)
}